// round 11
// baseline (speedup 1.0000x reference)
#include <cuda_runtime.h>
#include <cstdint>
#include <cstdio>

#define HDIM 64

static const int NMAX = 100000;
static const int EMAX = 1600000;
static const int SCANB = 1024;
static const int NBLK = (NMAX + SCANB - 1) / SCANB;   // 98

// ---------------- device scratch (allocation-free rule) ----------------
__device__ __align__(16) int   g_cnt[NMAX];
__device__ __align__(16) int   g_rowptr[NMAX];
__device__ __align__(16) int   g_cursor[NMAX];
__device__ __align__(16) int   g_bsum[NBLK];
__device__ __align__(16) int   g_boff[NBLK];
__device__ __align__(16) float g_dinv[NMAX];
__device__ __align__(16) int   g_csr_src[EMAX];
__device__ __align__(16) float g_csr_norm[EMAX];
__device__ __align__(16) float g_ht[(size_t)NMAX * HDIM];
__device__ __align__(16) float g_bufA[(size_t)NMAX * HDIM];
__device__ __align__(16) float g_bufB[(size_t)NMAX * HDIM];

// ---------------- prep: degree histogram, dinv, scan, CSR scatter ----------------
__global__ void hist_kernel(const int* __restrict__ ei, int E) {
    int e = blockIdx.x * blockDim.x + threadIdx.x;
    if (e >= E) return;
    atomicAdd(&g_cnt[ei[(size_t)E + e]], 1);
}

// block-level inclusive scan -> exclusive partials + block sums; also dinv
__global__ void scan1_kernel(int N) {
    __shared__ int s[SCANB];
    int t = threadIdx.x;
    int i = blockIdx.x * SCANB + t;
    int v = (i < N) ? g_cnt[i] : 0;
    if (i < N) g_dinv[i] = rsqrtf((float)v + 1.0f);  // +1 = self loop
    s[t] = v;
    __syncthreads();
#pragma unroll
    for (int off = 1; off < SCANB; off <<= 1) {
        int a = (t >= off) ? s[t - off] : 0;
        __syncthreads();
        s[t] += a;
        __syncthreads();
    }
    if (i < N) g_rowptr[i] = s[t] - v;   // exclusive
    if (t == SCANB - 1) g_bsum[blockIdx.x] = s[t];
}

// single-block parallel scan of block sums (nb <= 128)
__global__ void scan2_kernel(int nb) {
    __shared__ int s[128];
    int t = threadIdx.x;
    int v = (t < nb) ? g_bsum[t] : 0;
    s[t] = v;
    __syncthreads();
#pragma unroll
    for (int off = 1; off < 128; off <<= 1) {
        int a = (t >= off) ? s[t - off] : 0;
        __syncthreads();
        s[t] += a;
        __syncthreads();
    }
    if (t < nb) g_boff[t] = s[t] - v;    // exclusive
}

__global__ void scan3_kernel(int N) {
    int i = blockIdx.x * blockDim.x + threadIdx.x;
    if (i >= N) return;
    int r = g_rowptr[i] + g_boff[i >> 10];
    g_rowptr[i] = r;
    g_cursor[i] = r;
}

__global__ void scatter_csr_kernel(const int* __restrict__ ei, int E) {
    int e = blockIdx.x * blockDim.x + threadIdx.x;
    if (e >= E) return;
    int s = ei[e];
    int d = ei[(size_t)E + e];
    int pos = atomicAdd(&g_cursor[d], 1);
    g_csr_src[pos]  = s;
    g_csr_norm[pos] = g_dinv[s] * g_dinv[d];
}

// ---------------- GEMM: HT = act(X) @ W  (packed fp32x2 FMA, col-pair form)
// BM=128 rows x 64 cols per block, 128 threads; thread tile 8 rows x 8 cols.
// Same structure as the proven R6 kernel (non-duplicated tiles, mov.b64 dup-packs),
// scaled to halve LDS bytes per MAC (2 B/MAC -> 1 B/MAC).
template <int DIN, bool RELU_IN>
__global__ void __launch_bounds__(128) gemm_kernel(const float* __restrict__ X,
                                                   const float* __restrict__ W,
                                                   float* __restrict__ HT,
                                                   int N) {
    __shared__ __align__(16) float Xs[16][128];
    __shared__ __align__(16) float Ws[16][64];

    const int t   = threadIdx.x;      // 0..127
    const int rg  = t >> 3;           // 0..15 (row group of 8)
    const int cg  = t & 7;            // 0..7  (col group of 8)
    const int row0 = blockIdx.x * 128;

    unsigned long long acc[8][4];     // [row i][col pair j]
#pragma unroll
    for (int i = 0; i < 8; i++)
#pragma unroll
        for (int j = 0; j < 4; j++) acc[i][j] = 0ull;

    for (int k0 = 0; k0 < DIN; k0 += 16) {
        // load X tile: 128 rows x 16 k (each thread: 4 float4), transposed store
#pragma unroll
        for (int l = 0; l < 4; l++) {
            int idx = t + l * 128;            // 0..511
            int r   = idx >> 2;               // 0..127
            int kk  = (idx & 3) * 4;          // 0,4,8,12
            int grow = row0 + r;
            float4 v = make_float4(0.f, 0.f, 0.f, 0.f);
            if (grow < N)
                v = *(const float4*)&X[(size_t)grow * DIN + k0 + kk];
            if (RELU_IN) {
                v.x = fmaxf(v.x, 0.f); v.y = fmaxf(v.y, 0.f);
                v.z = fmaxf(v.z, 0.f); v.w = fmaxf(v.w, 0.f);
            }
            Xs[kk + 0][r] = v.x;
            Xs[kk + 1][r] = v.y;
            Xs[kk + 2][r] = v.z;
            Xs[kk + 3][r] = v.w;
        }
        // load W tile: 16 x 64 floats (each thread: two float4)
        {
#pragma unroll
            for (int i = 0; i < 2; i++) {
                int idx = t + i * 128;        // float4 index, 0..255
                int kk  = idx >> 4;           // 0..15
                int c   = (idx & 15) * 4;     // 0..60
                float4 w = *(const float4*)&W[(size_t)(k0 + kk) * HDIM + c];
                *(float4*)&Ws[kk][c] = w;
            }
        }
        __syncthreads();

#pragma unroll
        for (int kk = 0; kk < 16; kk++) {
            float4 xa = *(const float4*)&Xs[kk][rg * 8];       // rows 0..3
            float4 xb = *(const float4*)&Xs[kk][rg * 8 + 4];   // rows 4..7
            ulonglong2 wa = *(const ulonglong2*)&Ws[kk][cg * 8];     // {w0,w1},{w2,w3}
            ulonglong2 wb = *(const ulonglong2*)&Ws[kk][cg * 8 + 4]; // {w4,w5},{w6,w7}
            unsigned int xr[8] = {__float_as_uint(xa.x), __float_as_uint(xa.y),
                                  __float_as_uint(xa.z), __float_as_uint(xa.w),
                                  __float_as_uint(xb.x), __float_as_uint(xb.y),
                                  __float_as_uint(xb.z), __float_as_uint(xb.w)};
#pragma unroll
            for (int i = 0; i < 8; i++) {
                unsigned long long xp;
                asm("mov.b64 %0, {%1, %1};" : "=l"(xp) : "r"(xr[i]));
                asm("fma.rn.f32x2 %0, %1, %2, %0;" : "+l"(acc[i][0]) : "l"(xp), "l"(wa.x));
                asm("fma.rn.f32x2 %0, %1, %2, %0;" : "+l"(acc[i][1]) : "l"(xp), "l"(wa.y));
                asm("fma.rn.f32x2 %0, %1, %2, %0;" : "+l"(acc[i][2]) : "l"(xp), "l"(wb.x));
                asm("fma.rn.f32x2 %0, %1, %2, %0;" : "+l"(acc[i][3]) : "l"(xp), "l"(wb.y));
            }
        }
        __syncthreads();
    }

    // epilogue: 8 rows x 8 cols per thread
#pragma unroll
    for (int i = 0; i < 8; i++) {
        int grow = row0 + rg * 8 + i;
        if (grow < N) {
            unsigned int u[8];
#pragma unroll
            for (int j = 0; j < 4; j++)
                asm("mov.b64 {%0, %1}, %2;" : "=r"(u[2*j]), "=r"(u[2*j+1]) : "l"(acc[i][j]));
            float4 h0 = make_float4(__uint_as_float(u[0]), __uint_as_float(u[1]),
                                    __uint_as_float(u[2]), __uint_as_float(u[3]));
            float4 h1 = make_float4(__uint_as_float(u[4]), __uint_as_float(u[5]),
                                    __uint_as_float(u[6]), __uint_as_float(u[7]));
            *(float4*)&HT[(size_t)grow * HDIM + cg * 8]     = h0;
            *(float4*)&HT[(size_t)grow * HDIM + cg * 8 + 4] = h1;
        }
    }
}

// ---------------- aggregate: OUT[d] = bias + HT[d]*dinv[d]^2 + sum_e HT[src_e]*norm_e
// 16 threads per node, each owns one float4 of the 64-wide row.
__global__ void aggregate_kernel(const float* __restrict__ HT,
                                 const float* __restrict__ bias,
                                 float* __restrict__ OUT,
                                 int N) {
    int idx  = blockIdx.x * blockDim.x + threadIdx.x;
    int node = idx >> 4;
    int lane = idx & 15;
    if (node >= N) return;

    int start = g_rowptr[node];
    int cnt   = g_cnt[node];

    float4 a0 = make_float4(0.f, 0.f, 0.f, 0.f);
    float4 a1 = make_float4(0.f, 0.f, 0.f, 0.f);

    int i = 0;
    for (; i + 2 <= cnt; i += 2) {
        int e0 = start + i, e1 = start + i + 1;
        int s0 = g_csr_src[e0], s1 = g_csr_src[e1];
        float n0 = g_csr_norm[e0], n1 = g_csr_norm[e1];
        float4 v0 = *(const float4*)&HT[(size_t)s0 * HDIM + lane * 4];
        float4 v1 = *(const float4*)&HT[(size_t)s1 * HDIM + lane * 4];
        a0.x += v0.x * n0; a0.y += v0.y * n0; a0.z += v0.z * n0; a0.w += v0.w * n0;
        a1.x += v1.x * n1; a1.y += v1.y * n1; a1.z += v1.z * n1; a1.w += v1.w * n1;
    }
    if (i < cnt) {
        int e0 = start + i;
        int s0 = g_csr_src[e0];
        float n0 = g_csr_norm[e0];
        float4 v0 = *(const float4*)&HT[(size_t)s0 * HDIM + lane * 4];
        a0.x += v0.x * n0; a0.y += v0.y * n0; a0.z += v0.z * n0; a0.w += v0.w * n0;
    }
    a0.x += a1.x; a0.y += a1.y; a0.z += a1.z; a0.w += a1.w;

    float di = g_dinv[node];
    float d2 = di * di;
    float4 h  = *(const float4*)&HT[(size_t)node * HDIM + lane * 4];
    float4 bb = *(const float4*)&bias[lane * 4];
    float4 o;
    o.x = bb.x + h.x * d2 + a0.x;
    o.y = bb.y + h.y * d2 + a0.y;
    o.z = bb.z + h.z * d2 + a0.z;
    o.w = bb.w + h.w * d2 + a0.w;
    *(float4*)&OUT[(size_t)node * HDIM + lane * 4] = o;
}

// ---------------- aggregate3 fused with relu + FC(64->2) + log_softmax ----------------
__global__ void aggregate_fc_kernel(const float* __restrict__ HT,
                                    const float* __restrict__ bias,
                                    const float* __restrict__ Wfc,
                                    const float* __restrict__ bfc,
                                    float* __restrict__ out,
                                    int N) {
    int idx  = blockIdx.x * blockDim.x + threadIdx.x;
    int node = idx >> 4;
    int lane = idx & 15;
    if (node >= N) return;

    int start = g_rowptr[node];
    int cnt   = g_cnt[node];

    float4 a0 = make_float4(0.f, 0.f, 0.f, 0.f);
    float4 a1 = make_float4(0.f, 0.f, 0.f, 0.f);

    int i = 0;
    for (; i + 2 <= cnt; i += 2) {
        int e0 = start + i, e1 = start + i + 1;
        int s0 = g_csr_src[e0], s1 = g_csr_src[e1];
        float n0 = g_csr_norm[e0], n1 = g_csr_norm[e1];
        float4 v0 = *(const float4*)&HT[(size_t)s0 * HDIM + lane * 4];
        float4 v1 = *(const float4*)&HT[(size_t)s1 * HDIM + lane * 4];
        a0.x += v0.x * n0; a0.y += v0.y * n0; a0.z += v0.z * n0; a0.w += v0.w * n0;
        a1.x += v1.x * n1; a1.y += v1.y * n1; a1.z += v1.z * n1; a1.w += v1.w * n1;
    }
    if (i < cnt) {
        int e0 = start + i;
        int s0 = g_csr_src[e0];
        float n0 = g_csr_norm[e0];
        float4 v0 = *(const float4*)&HT[(size_t)s0 * HDIM + lane * 4];
        a0.x += v0.x * n0; a0.y += v0.y * n0; a0.z += v0.z * n0; a0.w += v0.w * n0;
    }
    a0.x += a1.x; a0.y += a1.y; a0.z += a1.z; a0.w += a1.w;

    float di = g_dinv[node];
    float d2 = di * di;
    float4 h  = *(const float4*)&HT[(size_t)node * HDIM + lane * 4];
    float4 bb = *(const float4*)&bias[lane * 4];
    // layer-3 output features for this lane's 4 columns, after relu
    float f0 = fmaxf(bb.x + h.x * d2 + a0.x, 0.f);
    float f1 = fmaxf(bb.y + h.y * d2 + a0.y, 0.f);
    float f2 = fmaxf(bb.z + h.z * d2 + a0.z, 0.f);
    float f3 = fmaxf(bb.w + h.w * d2 + a0.w, 0.f);

    // partial logits from this lane's 4 columns
    int c0 = lane * 4;
    float4 w0 = *(const float4*)&Wfc[(c0 + 0) * 2];
    float4 w1 = *(const float4*)&Wfc[(c0 + 2) * 2];
    float l0 = f0 * w0.x + f1 * w0.z + f2 * w1.x + f3 * w1.z;
    float l1 = f0 * w0.y + f1 * w0.w + f2 * w1.y + f3 * w1.w;

    // reduce across the 16-lane group (aligned within warp)
#pragma unroll
    for (int off = 8; off > 0; off >>= 1) {
        l0 += __shfl_down_sync(0xffffffffu, l0, off);
        l1 += __shfl_down_sync(0xffffffffu, l1, off);
    }
    if (lane == 0) {
        l0 += bfc[0];
        l1 += bfc[1];
        float m = fmaxf(l0, l1);
        float lse = m + logf(expf(l0 - m) + expf(l1 - m));
        out[(size_t)node * 2 + 0] = l0 - lse;
        out[(size_t)node * 2 + 1] = l1 - lse;
    }
}

// ---------------- launch ----------------
extern "C" void kernel_launch(void* const* d_in, const int* in_sizes, int n_in,
                              void* d_out, int out_size) {
    const float* x   = (const float*)d_in[0];
    const int*   ei  = (const int*)d_in[1];   // int32 (JAX x64 disabled)
    const float* W1  = (const float*)d_in[2];
    const float* b1  = (const float*)d_in[3];
    const float* W2  = (const float*)d_in[4];
    const float* b2  = (const float*)d_in[5];
    const float* W3  = (const float*)d_in[6];
    const float* b3  = (const float*)d_in[7];
    const float* Wfc = (const float*)d_in[8];
    const float* bfc = (const float*)d_in[9];

    const int Hh = in_sizes[3];            // 64
    const int D  = in_sizes[2] / Hh;       // 128
    const int N  = in_sizes[0] / D;        // 100000
    const int E  = in_sizes[1] / 2;        // 1600000

    float *ht, *bufA, *bufB;
    int* cnt;
    cudaGetSymbolAddress((void**)&ht,   g_ht);
    cudaGetSymbolAddress((void**)&bufA, g_bufA);
    cudaGetSymbolAddress((void**)&bufB, g_bufB);
    cudaGetSymbolAddress((void**)&cnt,  g_cnt);

    const int nb = (N + SCANB - 1) / SCANB;
    const int gblocks = (N + 127) / 128;
    const int ablocks = (N * 16 + 255) / 256;

    // CSR build, with gemm1 interleaved at kernel slot #4 so ncu captures it.
    cudaMemsetAsync(cnt, 0, (size_t)N * sizeof(int));
    hist_kernel<<<(E + 255) / 256, 256>>>(ei, E);                 // #1
    scan1_kernel<<<nb, SCANB>>>(N);                               // #2
    scan2_kernel<<<1, 128>>>(nb);                                 // #3
    gemm_kernel<128, false><<<gblocks, 128>>>(x, W1, ht, N);      // #4 (ncu slot)
    scan3_kernel<<<(N + 255) / 256, 256>>>(N);                    // #5
    scatter_csr_kernel<<<(E + 255) / 256, 256>>>(ei, E);          // #6

    // layer 1 aggregate
    aggregate_kernel<<<ablocks, 256>>>(ht, b1, bufA, N);
    // layer 2
    gemm_kernel<64, true><<<gblocks, 128>>>(bufA, W2, ht, N);
    aggregate_kernel<<<ablocks, 256>>>(ht, b2, bufB, N);
    // layer 3 (aggregate fused with FC + log_softmax)
    gemm_kernel<64, true><<<gblocks, 128>>>(bufB, W3, ht, N);
    aggregate_fc_kernel<<<ablocks, 256>>>(ht, b3, Wfc, bfc, (float*)d_out, N);
}

// round 12
// speedup vs baseline: 1.0872x; 1.0872x over previous
#include <cuda_runtime.h>
#include <cstdint>
#include <cstdio>

#define HDIM 64

static const int NMAX = 100000;
static const int EMAX = 1600000;
static const int SCANB = 1024;
static const int NBLK = (NMAX + SCANB - 1) / SCANB;   // 98

// ---------------- device scratch (allocation-free rule) ----------------
__device__ __align__(16) int   g_cnt[NMAX];
__device__ __align__(16) int   g_rowptr[NMAX];
__device__ __align__(16) int   g_cursor[NMAX];
__device__ __align__(16) int   g_bsum[NBLK];
__device__ __align__(16) int   g_boff[NBLK];
__device__ __align__(16) float g_dinv[NMAX];
__device__ __align__(16) int   g_csr_src[EMAX];
__device__ __align__(16) float g_csr_norm[EMAX];
__device__ __align__(16) float g_ht[(size_t)NMAX * HDIM];
__device__ __align__(16) float g_bufA[(size_t)NMAX * HDIM];
__device__ __align__(16) float g_bufB[(size_t)NMAX * HDIM];

// ---------------- prep: degree histogram, dinv, scan, CSR scatter ----------------
__global__ void hist_kernel(const int* __restrict__ ei, int E) {
    int e = blockIdx.x * blockDim.x + threadIdx.x;
    if (e >= E) return;
    atomicAdd(&g_cnt[ei[(size_t)E + e]], 1);
}

// block-level inclusive scan -> exclusive partials + block sums; also dinv
__global__ void scan1_kernel(int N) {
    __shared__ int s[SCANB];
    int t = threadIdx.x;
    int i = blockIdx.x * SCANB + t;
    int v = (i < N) ? g_cnt[i] : 0;
    if (i < N) g_dinv[i] = rsqrtf((float)v + 1.0f);  // +1 = self loop
    s[t] = v;
    __syncthreads();
#pragma unroll
    for (int off = 1; off < SCANB; off <<= 1) {
        int a = (t >= off) ? s[t - off] : 0;
        __syncthreads();
        s[t] += a;
        __syncthreads();
    }
    if (i < N) g_rowptr[i] = s[t] - v;   // exclusive
    if (t == SCANB - 1) g_bsum[blockIdx.x] = s[t];
}

// single-block parallel scan of block sums (nb <= 128)
__global__ void scan2_kernel(int nb) {
    __shared__ int s[128];
    int t = threadIdx.x;
    int v = (t < nb) ? g_bsum[t] : 0;
    s[t] = v;
    __syncthreads();
#pragma unroll
    for (int off = 1; off < 128; off <<= 1) {
        int a = (t >= off) ? s[t - off] : 0;
        __syncthreads();
        s[t] += a;
        __syncthreads();
    }
    if (t < nb) g_boff[t] = s[t] - v;    // exclusive
}

__global__ void scan3_kernel(int N) {
    int i = blockIdx.x * blockDim.x + threadIdx.x;
    if (i >= N) return;
    int r = g_rowptr[i] + g_boff[i >> 10];
    g_rowptr[i] = r;
    g_cursor[i] = r;
}

__global__ void scatter_csr_kernel(const int* __restrict__ ei, int E) {
    int e = blockIdx.x * blockDim.x + threadIdx.x;
    if (e >= E) return;
    int s = ei[e];
    int d = ei[(size_t)E + e];
    int pos = atomicAdd(&g_cursor[d], 1);
    g_csr_src[pos]  = s;
    g_csr_norm[pos] = g_dinv[s] * g_dinv[d];
}

// ---------------- GEMM: HT = act(X) @ W  (packed fp32x2 FMA, col-pair form)
// BM=32 rows x 64 cols per block, 128 threads, 4 rows x 8 cols (4 f32x2 pairs) each.
// (R6 proven version: 52us on gemm1, occ 50%, the SIMT sweet spot.)
template <int DIN, bool RELU_IN>
__global__ void __launch_bounds__(128) gemm_kernel(const float* __restrict__ X,
                                                   const float* __restrict__ W,
                                                   float* __restrict__ HT,
                                                   int N) {
    __shared__ __align__(16) float Xs[16][32];
    __shared__ __align__(16) float Ws[16][64];

    const int t   = threadIdx.x;      // 0..127
    const int rg  = t >> 4;           // 0..7  (row group of 4)
    const int cg  = t & 15;           // 0..15 (col group of 4)
    const int row0 = blockIdx.x * 32;

    unsigned long long acc2[4][2];
#pragma unroll
    for (int i = 0; i < 4; i++) { acc2[i][0] = 0ull; acc2[i][1] = 0ull; }

    for (int k0 = 0; k0 < DIN; k0 += 16) {
        // load X tile: 32 rows x 16 k (each thread: one float4)
        {
            int r  = t >> 2;          // 0..31
            int kk = (t & 3) * 4;     // 0,4,8,12
            int grow = row0 + r;
            float4 v = make_float4(0.f, 0.f, 0.f, 0.f);
            if (grow < N)
                v = *(const float4*)&X[(size_t)grow * DIN + k0 + kk];
            if (RELU_IN) {
                v.x = fmaxf(v.x, 0.f); v.y = fmaxf(v.y, 0.f);
                v.z = fmaxf(v.z, 0.f); v.w = fmaxf(v.w, 0.f);
            }
            Xs[kk + 0][r] = v.x;
            Xs[kk + 1][r] = v.y;
            Xs[kk + 2][r] = v.z;
            Xs[kk + 3][r] = v.w;
        }
        // load W tile: 16 x 64 floats (each thread: two float4)
        {
#pragma unroll
            for (int i = 0; i < 2; i++) {
                int idx = t + i * 128;        // float4 index, 0..255
                int kk  = idx >> 4;           // 0..15
                int c   = (idx & 15) * 4;     // 0..60
                float4 w = *(const float4*)&W[(size_t)(k0 + kk) * HDIM + c];
                *(float4*)&Ws[kk][c] = w;
            }
        }
        __syncthreads();

#pragma unroll
        for (int kk = 0; kk < 16; kk++) {
            float4 xv = *(const float4*)&Xs[kk][rg * 4];
            ulonglong2 wv = *(const ulonglong2*)&Ws[kk][cg * 4]; // {w0,w1},{w2,w3}
            unsigned int xb[4] = {__float_as_uint(xv.x), __float_as_uint(xv.y),
                                  __float_as_uint(xv.z), __float_as_uint(xv.w)};
#pragma unroll
            for (int i = 0; i < 4; i++) {
                unsigned long long xp;
                asm("mov.b64 %0, {%1, %1};" : "=l"(xp) : "r"(xb[i]));
                asm("fma.rn.f32x2 %0, %1, %2, %0;" : "+l"(acc2[i][0]) : "l"(xp), "l"(wv.x));
                asm("fma.rn.f32x2 %0, %1, %2, %0;" : "+l"(acc2[i][1]) : "l"(xp), "l"(wv.y));
            }
        }
        __syncthreads();
    }

    // epilogue: write HT
#pragma unroll
    for (int i = 0; i < 4; i++) {
        int grow = row0 + rg * 4 + i;
        if (grow < N) {
            unsigned int u0, u1, u2, u3;
            asm("mov.b64 {%0, %1}, %2;" : "=r"(u0), "=r"(u1) : "l"(acc2[i][0]));
            asm("mov.b64 {%0, %1}, %2;" : "=r"(u2), "=r"(u3) : "l"(acc2[i][1]));
            float4 hv = make_float4(__uint_as_float(u0), __uint_as_float(u1),
                                    __uint_as_float(u2), __uint_as_float(u3));
            *(float4*)&HT[(size_t)grow * HDIM + cg * 4] = hv;
        }
    }
}

// ---------------- aggregate: OUT[d] = bias + HT[d]*dinv[d]^2 + sum_e HT[src_e]*norm_e
// 16 threads per node, each owns one float4 of the 64-wide row.
__global__ void aggregate_kernel(const float* __restrict__ HT,
                                 const float* __restrict__ bias,
                                 float* __restrict__ OUT,
                                 int N) {
    int idx  = blockIdx.x * blockDim.x + threadIdx.x;
    int node = idx >> 4;
    int lane = idx & 15;
    if (node >= N) return;

    int start = g_rowptr[node];
    int cnt   = g_cnt[node];

    float4 a0 = make_float4(0.f, 0.f, 0.f, 0.f);
    float4 a1 = make_float4(0.f, 0.f, 0.f, 0.f);

    int i = 0;
    for (; i + 2 <= cnt; i += 2) {
        int e0 = start + i, e1 = start + i + 1;
        int s0 = g_csr_src[e0], s1 = g_csr_src[e1];
        float n0 = g_csr_norm[e0], n1 = g_csr_norm[e1];
        float4 v0 = *(const float4*)&HT[(size_t)s0 * HDIM + lane * 4];
        float4 v1 = *(const float4*)&HT[(size_t)s1 * HDIM + lane * 4];
        a0.x += v0.x * n0; a0.y += v0.y * n0; a0.z += v0.z * n0; a0.w += v0.w * n0;
        a1.x += v1.x * n1; a1.y += v1.y * n1; a1.z += v1.z * n1; a1.w += v1.w * n1;
    }
    if (i < cnt) {
        int e0 = start + i;
        int s0 = g_csr_src[e0];
        float n0 = g_csr_norm[e0];
        float4 v0 = *(const float4*)&HT[(size_t)s0 * HDIM + lane * 4];
        a0.x += v0.x * n0; a0.y += v0.y * n0; a0.z += v0.z * n0; a0.w += v0.w * n0;
    }
    a0.x += a1.x; a0.y += a1.y; a0.z += a1.z; a0.w += a1.w;

    float di = g_dinv[node];
    float d2 = di * di;
    float4 h  = *(const float4*)&HT[(size_t)node * HDIM + lane * 4];
    float4 bb = *(const float4*)&bias[lane * 4];
    float4 o;
    o.x = bb.x + h.x * d2 + a0.x;
    o.y = bb.y + h.y * d2 + a0.y;
    o.z = bb.z + h.z * d2 + a0.z;
    o.w = bb.w + h.w * d2 + a0.w;
    *(float4*)&OUT[(size_t)node * HDIM + lane * 4] = o;
}

// ---------------- aggregate3 fused with relu + FC(64->2) + log_softmax ----------------
__global__ void aggregate_fc_kernel(const float* __restrict__ HT,
                                    const float* __restrict__ bias,
                                    const float* __restrict__ Wfc,
                                    const float* __restrict__ bfc,
                                    float* __restrict__ out,
                                    int N) {
    int idx  = blockIdx.x * blockDim.x + threadIdx.x;
    int node = idx >> 4;
    int lane = idx & 15;
    if (node >= N) return;

    int start = g_rowptr[node];
    int cnt   = g_cnt[node];

    float4 a0 = make_float4(0.f, 0.f, 0.f, 0.f);
    float4 a1 = make_float4(0.f, 0.f, 0.f, 0.f);

    int i = 0;
    for (; i + 2 <= cnt; i += 2) {
        int e0 = start + i, e1 = start + i + 1;
        int s0 = g_csr_src[e0], s1 = g_csr_src[e1];
        float n0 = g_csr_norm[e0], n1 = g_csr_norm[e1];
        float4 v0 = *(const float4*)&HT[(size_t)s0 * HDIM + lane * 4];
        float4 v1 = *(const float4*)&HT[(size_t)s1 * HDIM + lane * 4];
        a0.x += v0.x * n0; a0.y += v0.y * n0; a0.z += v0.z * n0; a0.w += v0.w * n0;
        a1.x += v1.x * n1; a1.y += v1.y * n1; a1.z += v1.z * n1; a1.w += v1.w * n1;
    }
    if (i < cnt) {
        int e0 = start + i;
        int s0 = g_csr_src[e0];
        float n0 = g_csr_norm[e0];
        float4 v0 = *(const float4*)&HT[(size_t)s0 * HDIM + lane * 4];
        a0.x += v0.x * n0; a0.y += v0.y * n0; a0.z += v0.z * n0; a0.w += v0.w * n0;
    }
    a0.x += a1.x; a0.y += a1.y; a0.z += a1.z; a0.w += a1.w;

    float di = g_dinv[node];
    float d2 = di * di;
    float4 h  = *(const float4*)&HT[(size_t)node * HDIM + lane * 4];
    float4 bb = *(const float4*)&bias[lane * 4];
    // layer-3 output features for this lane's 4 columns, after relu
    float f0 = fmaxf(bb.x + h.x * d2 + a0.x, 0.f);
    float f1 = fmaxf(bb.y + h.y * d2 + a0.y, 0.f);
    float f2 = fmaxf(bb.z + h.z * d2 + a0.z, 0.f);
    float f3 = fmaxf(bb.w + h.w * d2 + a0.w, 0.f);

    // partial logits from this lane's 4 columns
    int c0 = lane * 4;
    float4 w0 = *(const float4*)&Wfc[(c0 + 0) * 2];
    float4 w1 = *(const float4*)&Wfc[(c0 + 2) * 2];
    float l0 = f0 * w0.x + f1 * w0.z + f2 * w1.x + f3 * w1.z;
    float l1 = f0 * w0.y + f1 * w0.w + f2 * w1.y + f3 * w1.w;

    // reduce across the 16-lane group (aligned within warp)
#pragma unroll
    for (int off = 8; off > 0; off >>= 1) {
        l0 += __shfl_down_sync(0xffffffffu, l0, off);
        l1 += __shfl_down_sync(0xffffffffu, l1, off);
    }
    if (lane == 0) {
        l0 += bfc[0];
        l1 += bfc[1];
        float m = fmaxf(l0, l1);
        float lse = m + logf(expf(l0 - m) + expf(l1 - m));
        out[(size_t)node * 2 + 0] = l0 - lse;
        out[(size_t)node * 2 + 1] = l1 - lse;
    }
}

// ---------------- launch ----------------
extern "C" void kernel_launch(void* const* d_in, const int* in_sizes, int n_in,
                              void* d_out, int out_size) {
    const float* x   = (const float*)d_in[0];
    const int*   ei  = (const int*)d_in[1];   // int32 (JAX x64 disabled)
    const float* W1  = (const float*)d_in[2];
    const float* b1  = (const float*)d_in[3];
    const float* W2  = (const float*)d_in[4];
    const float* b2  = (const float*)d_in[5];
    const float* W3  = (const float*)d_in[6];
    const float* b3  = (const float*)d_in[7];
    const float* Wfc = (const float*)d_in[8];
    const float* bfc = (const float*)d_in[9];

    const int Hh = in_sizes[3];            // 64
    const int D  = in_sizes[2] / Hh;       // 128
    const int N  = in_sizes[0] / D;        // 100000
    const int E  = in_sizes[1] / 2;        // 1600000

    float *ht, *bufA, *bufB;
    int* cnt;
    cudaGetSymbolAddress((void**)&ht,   g_ht);
    cudaGetSymbolAddress((void**)&bufA, g_bufA);
    cudaGetSymbolAddress((void**)&bufB, g_bufB);
    cudaGetSymbolAddress((void**)&cnt,  g_cnt);

    // Lazy one-time stream/event creation (first call is the uncaptured
    // correctness run; resources are reused inside the captured graph).
    static cudaStream_t sPrep = nullptr;
    static cudaEvent_t  eFork = nullptr, eJoin = nullptr;
    if (sPrep == nullptr) {
        cudaStreamCreateWithFlags(&sPrep, cudaStreamNonBlocking);
        cudaEventCreateWithFlags(&eFork, cudaEventDisableTiming);
        cudaEventCreateWithFlags(&eJoin, cudaEventDisableTiming);
    }

    const int nb = (N + SCANB - 1) / SCANB;
    const int gblocks = (N + 31) / 32;
    const int ablocks = (N * 16 + 255) / 256;

    // Fork: CSR build on sPrep, concurrent with gemm1 on the main stream.
    cudaEventRecord(eFork, 0);
    cudaStreamWaitEvent(sPrep, eFork, 0);

    // --- prep branch (independent of gemm1) ---
    cudaMemsetAsync(cnt, 0, (size_t)N * sizeof(int), sPrep);
    hist_kernel<<<(E + 255) / 256, 256, 0, sPrep>>>(ei, E);
    scan1_kernel<<<nb, SCANB, 0, sPrep>>>(N);
    scan2_kernel<<<1, 128, 0, sPrep>>>(nb);
    scan3_kernel<<<(N + 255) / 256, 256, 0, sPrep>>>(N);
    scatter_csr_kernel<<<(E + 255) / 256, 256, 0, sPrep>>>(ei, E);
    cudaEventRecord(eJoin, sPrep);

    // --- main branch ---
    gemm_kernel<128, false><<<gblocks, 128>>>(x, W1, ht, N);

    // Join: aggregate1 needs both gemm1 (main) and CSR (sPrep).
    cudaStreamWaitEvent(0, eJoin, 0);

    aggregate_kernel<<<ablocks, 256>>>(ht, b1, bufA, N);
    // layer 2
    gemm_kernel<64, true><<<gblocks, 128>>>(bufA, W2, ht, N);
    aggregate_kernel<<<ablocks, 256>>>(ht, b2, bufB, N);
    // layer 3 (aggregate fused with FC + log_softmax)
    gemm_kernel<64, true><<<gblocks, 128>>>(bufB, W3, ht, N);
    aggregate_fc_kernel<<<ablocks, 256>>>(ht, b3, Wfc, bfc, (float*)d_out, N);
}